// round 2
// baseline (speedup 1.0000x reference)
#include <cuda_runtime.h>
#include <cstdint>
#include <cstddef>

// Problem shape (fixed by setup_inputs): B=64, S=2048, D=512, fp32.
// Outputs (tuple, flattened in order): d_prime [64*512], probs [64*2048], logit [64*2048].
#define B_ 64
#define S_ 2048
#define D_ 512
#define CCLIP 10.0f

#define OUT_DP 0
#define OUT_PROBS (B_ * D_)                 // 32768
#define OUT_LOGIT (B_ * D_ + B_ * S_)       // 163840

// Scratch (static __device__ — no allocations allowed)
__device__ float g_q[B_ * D_];          // q = tgt @ W_q^T            (128 KB)
__device__ float g_upart[4 * B_ * S_];  // per-d-chunk partial u      (2 MB)
__device__ float g_dppart[8 * B_ * D_]; // per-s-chunk partial d'     (1 MB)

typedef unsigned long long ull;

// sm_100+ packed fp32 FMA (2 independent FMAs per instruction)
__device__ __forceinline__ void ffma2(ull& acc, ull a, ull b) {
    asm("fma.rn.f32x2 %0, %1, %2, %0;" : "+l"(acc) : "l"(a), "l"(b));
}
__device__ __forceinline__ ull pack2(float x, float y) {
    ull r; asm("mov.b64 %0, {%1, %2};" : "=l"(r) : "f"(x), "f"(y)); return r;
}
__device__ __forceinline__ float2 unpack2(ull x) {
    float2 f; asm("mov.b64 {%0, %1}, %2;" : "=f"(f.x), "=f"(f.y) : "l"(x)); return f;
}

// ---------------------------------------------------------------------------
// Kernel A: q[b,d] = sum_k tgt[b,k] * W_q[d,k].  Tiny (34 MFLOP).
// One block per d; W_q row cached in smem (read exactly once from HBM).
// ---------------------------------------------------------------------------
__global__ void qproj_kernel(const float* __restrict__ tgt,
                             const float* __restrict__ Wq) {
    __shared__ float wrow[D_];
    const int d = blockIdx.x;
    for (int i = threadIdx.x; i < D_; i += blockDim.x) wrow[i] = Wq[d * D_ + i];
    __syncthreads();
    const int warp = threadIdx.x >> 5, lane = threadIdx.x & 31;
    for (int b = warp; b < B_; b += 8) {
        const float* t = tgt + b * D_;
        float p = 0.f;
        #pragma unroll 4
        for (int k = lane; k < D_; k += 32) p += t[k] * wrow[k];
        #pragma unroll
        for (int o = 16; o; o >>= 1) p += __shfl_xor_sync(0xffffffffu, p, o);
        if (lane == 0) g_q[b * D_ + d] = p;
    }
}

// ---------------------------------------------------------------------------
// Kernel B: fused main GEMM + tanh + v-reduction.
// Block computes ref[s0:s0+128, d0:d0+128] = src_tile @ W_ref_tile^T (K=512),
// then u_partial[s] = sum_{d in chunk} v[d] * tanh(q[b,d] + ref[s,d]).
// h is never written to HBM. 8x8 microtile per thread, s-dim packed in f32x2.
// Deterministic: partials written to g_upart (no atomics).
// ---------------------------------------------------------------------------
__global__ __launch_bounds__(256, 2)
void fused_kernel(const float* __restrict__ src,
                  const float* __restrict__ Wref,
                  const float* __restrict__ v) {
    __shared__ float As[16][132];    // [k][s] transposed src tile
    __shared__ float Bs[16][132];    // [k][d] transposed W_ref tile
    __shared__ float red[128][17];   // cross-tx reduction

    const int dz = blockIdx.x;   // d-chunk 0..3
    const int sz = blockIdx.y;   // s-tile 0..15
    const int b  = blockIdx.z;   // batch 0..63
    const int tid = threadIdx.x;
    const int tx = tid & 15;     // d microtile index
    const int ty = tid >> 4;     // s microtile index

    const float* srcB = src + ((size_t)b * S_ + (size_t)sz * 128) * D_;
    const float* wB   = Wref + (size_t)dz * 128 * D_;

    ull acc[4][8];
    #pragma unroll
    for (int p = 0; p < 4; ++p)
        #pragma unroll
        for (int c = 0; c < 8; ++c) acc[p][c] = 0ull;

    for (int k0 = 0; k0 < D_; k0 += 16) {
        // Cooperative tile load (float4, coalesced), transposed into smem.
        #pragma unroll
        for (int i = 0; i < 2; ++i) {
            const int idx = tid + i * 256;
            const int r = idx >> 2;          // row within tile (s or d)
            const int c4 = (idx & 3) << 2;   // k offset
            float4 va = *(const float4*)(srcB + (size_t)r * D_ + k0 + c4);
            As[c4 + 0][r] = va.x; As[c4 + 1][r] = va.y;
            As[c4 + 2][r] = va.z; As[c4 + 3][r] = va.w;
            float4 vb = *(const float4*)(wB + (size_t)r * D_ + k0 + c4);
            Bs[c4 + 0][r] = vb.x; Bs[c4 + 1][r] = vb.y;
            Bs[c4 + 2][r] = vb.z; Bs[c4 + 3][r] = vb.w;
        }
        __syncthreads();

        #pragma unroll
        for (int k = 0; k < 16; ++k) {
            // 4 packed s-pairs (already adjacent in smem — free packing)
            ull av[4];
            av[0] = *(const ull*)&As[k][ty * 8 + 0];
            av[1] = *(const ull*)&As[k][ty * 8 + 2];
            av[2] = *(const ull*)&As[k][ty * 8 + 4];
            av[3] = *(const ull*)&As[k][ty * 8 + 6];
            float4 w0 = *(const float4*)&Bs[k][tx * 8 + 0];
            float4 w1 = *(const float4*)&Bs[k][tx * 8 + 4];
            ull bv[8];
            bv[0] = pack2(w0.x, w0.x); bv[1] = pack2(w0.y, w0.y);
            bv[2] = pack2(w0.z, w0.z); bv[3] = pack2(w0.w, w0.w);
            bv[4] = pack2(w1.x, w1.x); bv[5] = pack2(w1.y, w1.y);
            bv[6] = pack2(w1.z, w1.z); bv[7] = pack2(w1.w, w1.w);
            #pragma unroll
            for (int p = 0; p < 4; ++p)
                #pragma unroll
                for (int c = 0; c < 8; ++c) ffma2(acc[p][c], av[p], bv[c]);
        }
        __syncthreads();
    }

    // Epilogue: h = tanh(q + ref); pu[s] = sum_c v[d]*h  (8 d's per thread)
    float qv[8], vv[8];
    #pragma unroll
    for (int c = 0; c < 8; ++c) {
        const int d = dz * 128 + tx * 8 + c;
        qv[c] = g_q[b * D_ + d];
        vv[c] = v[d];
    }
    float pu[8];
    #pragma unroll
    for (int p = 0; p < 4; ++p) {
        float s0 = 0.f, s1 = 0.f;
        #pragma unroll
        for (int c = 0; c < 8; ++c) {
            float2 r = unpack2(acc[p][c]);
            s0 += vv[c] * tanhf(qv[c] + r.x);
            s1 += vv[c] * tanhf(qv[c] + r.y);
        }
        pu[2 * p + 0] = s0;
        pu[2 * p + 1] = s1;
    }
    #pragma unroll
    for (int i = 0; i < 8; ++i) red[ty * 8 + i][tx] = pu[i];
    __syncthreads();
    if (tid < 128) {
        float s = 0.f;
        #pragma unroll
        for (int j = 0; j < 16; ++j) s += red[tid][j];
        g_upart[((size_t)dz * B_ + b) * S_ + sz * 128 + tid] = s;
    }
}

// ---------------------------------------------------------------------------
// Kernel C: u -> logit = C*tanh(u) -> softmax over S.  Writes logit + probs.
// Logits are bounded in [-C, C], so shift by the constant C (exact vs max-sub
// to fp rounding).  One block per batch; deterministic tree reduction.
// ---------------------------------------------------------------------------
__global__ void softmax_kernel(float* __restrict__ out) {
    const int b = blockIdx.x, tid = threadIdx.x;
    float* logit = out + OUT_LOGIT + b * S_;
    float* probs = out + OUT_PROBS + b * S_;
    __shared__ float red[256];

    float lsum = 0.f;
    for (int s = tid; s < S_; s += 256) {
        float u = 0.f;
        #pragma unroll
        for (int p = 0; p < 4; ++p) u += g_upart[((size_t)p * B_ + b) * S_ + s];
        const float l = CCLIP * tanhf(u);
        logit[s] = l;
        lsum += expf(l - CCLIP);
    }
    red[tid] = lsum;
    __syncthreads();
    for (int o = 128; o; o >>= 1) {
        if (tid < o) red[tid] += red[tid + o];
        __syncthreads();
    }
    const float inv = 1.f / red[0];
    for (int s = tid; s < S_; s += 256)
        probs[s] = expf(logit[s] - CCLIP) * inv;
}

// ---------------------------------------------------------------------------
// Kernel D: d'_partial[sc][b][d] = sum_{s in chunk} probs[b,s] * src[b,s,d].
// Streams src once more (256 MB). 512 blocks, coalesced along d.
// ---------------------------------------------------------------------------
__global__ void dprime_kernel(const float* __restrict__ src,
                              const float* __restrict__ out) {
    const float* probs = out + OUT_PROBS;
    const int sc = blockIdx.x;   // s-chunk 0..7 (256 rows each)
    const int b  = blockIdx.y;
    const int d  = threadIdx.x;  // 0..511
    __shared__ float p_sm[256];
    if (threadIdx.x < 256)
        p_sm[threadIdx.x] = probs[b * S_ + sc * 256 + threadIdx.x];
    __syncthreads();
    const float* sp = src + ((size_t)b * S_ + (size_t)sc * 256) * D_ + d;
    float acc = 0.f;
    #pragma unroll 4
    for (int s = 0; s < 256; ++s) acc += p_sm[s] * sp[(size_t)s * D_];
    g_dppart[((size_t)sc * B_ + b) * D_ + d] = acc;
}

// Kernel E: sum the 8 d' partials (deterministic order).
__global__ void dpsum_kernel(float* __restrict__ out) {
    const int b = blockIdx.x, d = threadIdx.x;
    float acc = 0.f;
    #pragma unroll
    for (int sc = 0; sc < 8; ++sc)
        acc += g_dppart[((size_t)sc * B_ + b) * D_ + d];
    out[OUT_DP + b * D_ + d] = acc;
}

// ---------------------------------------------------------------------------
extern "C" void kernel_launch(void* const* d_in, const int* in_sizes, int n_in,
                              void* d_out, int out_size) {
    const float* src  = (const float*)d_in[0];  // [64, 2048, 512]
    const float* tgt  = (const float*)d_in[1];  // [64, 1, 512]
    const float* Wq   = (const float*)d_in[2];  // [512, 512]
    const float* Wref = (const float*)d_in[3];  // [512, 512]
    const float* v    = (const float*)d_in[4];  // [512]
    float* out = (float*)d_out;

    qproj_kernel<<<D_, 256>>>(tgt, Wq);

    dim3 gB(4, 16, B_);                 // (d-chunks, s-tiles, batch)
    fused_kernel<<<gB, 256>>>(src, Wref, v);

    softmax_kernel<<<B_, 256>>>(out);

    dim3 gD(8, B_);                     // (s-chunks, batch)
    dprime_kernel<<<gD, 512>>>(src, out);

    dpsum_kernel<<<B_, D_>>>(out);
}

// round 6
// speedup vs baseline: 1.9305x; 1.9305x over previous
#include <cuda_runtime.h>
#include <cuda_bf16.h>
#include <cstdint>
#include <cstddef>

// Shape fixed by setup_inputs: B=64, S=2048, D=512, fp32.
// Outputs flattened: d_prime [64*512], probs [64*2048], logit [64*2048].
#define B_ 64
#define S_ 2048
#define D_ 512
#define CCLIP 10.0f
#define OUT_DP 0
#define OUT_PROBS (B_ * D_)
#define OUT_LOGIT (B_ * D_ + B_ * S_)

// ---- static device scratch (no allocations allowed) ----
__device__ float g_q[B_ * D_];            // q = tgt @ W_q^T
__device__ float g_u[B_ * S_];            // u logits pre-clip
__device__ float g_dppart[16 * B_ * D_];  // d' partials
// W_ref split hi/lo bf16, tiled: tile (n,kc) = [(n*4+kc)<<14 ..], in-tile
// row-major [d_local 128][k_local 128].
__device__ __align__(16) __nv_bfloat16 g_wh[4 * 4 * 128 * 128];
__device__ __align__(16) __nv_bfloat16 g_wl[4 * 4 * 128 * 128];

__device__ __forceinline__ uint32_t smem_u32(const void* p) {
    uint32_t a;
    asm("{ .reg .u64 t; cvta.to.shared.u64 t, %1; cvt.u32.u64 %0, t; }"
        : "=r"(a) : "l"(p));
    return a;
}

__device__ __forceinline__ void ldsm4(uint32_t* r, uint32_t addr) {
    asm volatile("ldmatrix.sync.aligned.m8n8.x4.shared.b16 {%0,%1,%2,%3}, [%4];"
        : "=r"(r[0]), "=r"(r[1]), "=r"(r[2]), "=r"(r[3]) : "r"(addr));
}

__device__ __forceinline__ void mma16816(float* c, const uint32_t* a,
                                         const uint32_t* b) {
    asm volatile(
        "mma.sync.aligned.m16n8k16.row.col.f32.bf16.bf16.f32 "
        "{%0,%1,%2,%3}, {%4,%5,%6,%7}, {%8,%9}, {%0,%1,%2,%3};"
        : "+f"(c[0]), "+f"(c[1]), "+f"(c[2]), "+f"(c[3])
        : "r"(a[0]), "r"(a[1]), "r"(a[2]), "r"(a[3]), "r"(b[0]), "r"(b[1]));
}

__device__ __forceinline__ float fast_tanh(float x) {
    float e = __expf(2.0f * x);
    return 1.0f - __fdividef(2.0f, e + 1.0f);
}

// ===================================================================
// Kernel A: q[b,d] = sum_k tgt[b,k] * W_q[d,k]  (tiny)
// ===================================================================
__global__ void qproj_kernel(const float* __restrict__ tgt,
                             const float* __restrict__ Wq) {
    __shared__ float wrow[D_];
    const int d = blockIdx.x;
    for (int i = threadIdx.x; i < D_; i += blockDim.x) wrow[i] = Wq[d * D_ + i];
    __syncthreads();
    const int warp = threadIdx.x >> 5, lane = threadIdx.x & 31;
    for (int b = warp; b < B_; b += 8) {
        const float* t = tgt + b * D_;
        float p = 0.f;
        #pragma unroll 4
        for (int k = lane; k < D_; k += 32) p += t[k] * wrow[k];
        #pragma unroll
        for (int o = 16; o; o >>= 1) p += __shfl_xor_sync(0xffffffffu, p, o);
        if (lane == 0) g_q[b * D_ + d] = p;
    }
}

// ===================================================================
// Kernel W: split W_ref into hi/lo bf16, tiled layout.
// ===================================================================
__global__ void wsplit_kernel(const float* __restrict__ Wref) {
    const int i = blockIdx.x * blockDim.x + threadIdx.x;  // 0 .. 262143
    const float w = Wref[i];
    const int d = i >> 9, k = i & 511;
    const int n = d >> 7, dl = d & 127;
    const int kc = k >> 7, kl = k & 127;
    const int off = (((n << 2) | kc) << 14) + dl * 128 + kl;
    __nv_bfloat16 hi = __float2bfloat16(w);
    g_wh[off] = hi;
    g_wl[off] = __float2bfloat16(w - __bfloat162float(hi));
}

// ===================================================================
// Kernel B: split-bf16 mma.sync GEMM + fused tanh/v-reduction.
// One CTA per (b, 128-s-row tile). 8 warps: 4 along s (32 each), 2 along d.
// For each of 4 d-chunks (n): acc[128x128] fp32 in regs, K=512 in 4 chunks,
// 3 passes (Ah*Bh, Ah*Bl, Al*Bh). Epilogue accumulates u per s-row.
// ===================================================================
#define A_STRIDE 136                      // bf16 elems per smem row (pad 8)
#define SM_AH 0
#define SM_AL 34816
#define SM_BH 69632
#define SM_BL 104448
#define SM_SQ 139264
#define SM_SV 141312
#define SM_U  143360
#define SM_TOTAL 144384

__global__ __launch_bounds__(256)
void fused_mma_kernel(const float* __restrict__ src,
                      const float* __restrict__ v) {
    extern __shared__ char smem[];
    const uint32_t sb = smem_u32(smem);
    const int tid = threadIdx.x, wid = tid >> 5, lane = tid & 31;
    const int warp_m = wid & 3, warp_n = wid >> 2;
    const int sz = blockIdx.x, b = blockIdx.y;

    float* sq = (float*)(smem + SM_SQ);
    float* sv = (float*)(smem + SM_SV);
    float* u_sm = (float*)(smem + SM_U);
    for (int i = tid; i < D_; i += 256) {
        sq[i] = g_q[b * D_ + i];
        sv[i] = v[i];
    }
    if (tid < 256) u_sm[tid] = 0.f;
    __syncthreads();

    const float* srcB = src + ((size_t)(b * S_ + sz * 128)) * D_;
    __nv_bfloat16* Ah = (__nv_bfloat16*)(smem + SM_AH);
    __nv_bfloat16* Al = (__nv_bfloat16*)(smem + SM_AL);

    // per-thread invariant ldmatrix offsets (in bf16 elems)
    const int a_row = (lane & 15), a_kh = (lane >> 4) * 8;
    const int b_row = (lane & 7) + ((lane >> 4) & 1) * 8;
    const int b_kh = ((lane >> 3) & 1) * 8;

    float acc[2][8][4];

    for (int n = 0; n < 4; ++n) {
        #pragma unroll
        for (int mt = 0; mt < 2; ++mt)
            #pragma unroll
            for (int nt = 0; nt < 8; ++nt)
                #pragma unroll
                for (int e = 0; e < 4; ++e) acc[mt][nt][e] = 0.f;

        for (int kc = 0; kc < 4; ++kc) {
            __syncthreads();   // previous mma reads of smem done
            // ---- convert A chunk [128 s][128 k] fp32 -> hi/lo bf16 ----
            #pragma unroll 4
            for (int i = 0; i < 16; ++i) {
                const int idx = tid + i * 256;        // 0..4095 float4s
                const int r = idx >> 5, c4 = (idx & 31) << 2;
                float4 x = *(const float4*)(srcB + (size_t)r * D_ + kc * 128 + c4);
                const int off = r * A_STRIDE + c4;
                __nv_bfloat162 h0 = __floats2bfloat162_rn(x.x, x.y);
                __nv_bfloat162 h1 = __floats2bfloat162_rn(x.z, x.w);
                *(__nv_bfloat162*)&Ah[off] = h0;
                *(__nv_bfloat162*)&Ah[off + 2] = h1;
                float lx = x.x - __low2float(h0), ly = x.y - __high2float(h0);
                float lz = x.z - __low2float(h1), lw = x.w - __high2float(h1);
                *(__nv_bfloat162*)&Al[off] = __floats2bfloat162_rn(lx, ly);
                *(__nv_bfloat162*)&Al[off + 2] = __floats2bfloat162_rn(lz, lw);
            }
            // ---- load B tile (n,kc) hi+lo from pre-split global ----
            {
                const int tb = ((n << 2) | kc) << 14;
                const uint4* gh = (const uint4*)(g_wh + tb);
                const uint4* gl = (const uint4*)(g_wl + tb);
                uint4* bh = (uint4*)(smem + SM_BH);
                uint4* bl = (uint4*)(smem + SM_BL);
                #pragma unroll
                for (int i = 0; i < 8; ++i) {
                    const int idx = tid + i * 256;    // 0..2047 vec8s
                    const int r = idx >> 4, vv = idx & 15;
                    // smem row stride 136 bf16 = 272B = 17 uint4
                    bh[r * 17 + vv] = gh[r * 16 + vv];
                    bl[r * 17 + vv] = gl[r * 16 + vv];
                }
            }
            __syncthreads();

            // ---- 3 passes x 8 k-steps of m16n8k16 ----
            #pragma unroll
            for (int pass = 0; pass < 3; ++pass) {
                const uint32_t aBase = sb + (pass == 2 ? SM_AL : SM_AH);
                const uint32_t bBase = sb + (pass == 1 ? SM_BL : SM_BH);
                #pragma unroll
                for (int ks = 0; ks < 8; ++ks) {
                    uint32_t af[2][4];
                    #pragma unroll
                    for (int mt = 0; mt < 2; ++mt) {
                        const int row = warp_m * 32 + mt * 16 + a_row;
                        ldsm4(af[mt],
                              aBase + (uint32_t)(row * A_STRIDE + ks * 16 + a_kh) * 2);
                    }
                    #pragma unroll
                    for (int ntp = 0; ntp < 4; ++ntp) {
                        uint32_t bf[4];
                        const int row = warp_n * 64 + ntp * 16 + b_row;
                        ldsm4(bf,
                              bBase + (uint32_t)(row * A_STRIDE + ks * 16 + b_kh) * 2);
                        #pragma unroll
                        for (int mt = 0; mt < 2; ++mt) {
                            mma16816(acc[mt][2 * ntp], af[mt], bf);
                            mma16816(acc[mt][2 * ntp + 1], af[mt], bf + 2);
                        }
                    }
                }
            }
        }

        // ---- epilogue for this d-chunk: u += sum_d v[d]*tanh(q[d]+pre) ----
        const int g = lane >> 2;
        #pragma unroll
        for (int mt = 0; mt < 2; ++mt) {
            float s0 = 0.f, s1 = 0.f;
            #pragma unroll
            for (int nt = 0; nt < 8; ++nt) {
                const int d = n * 128 + warp_n * 64 + nt * 8 + (lane & 3) * 2;
                const float* c = acc[mt][nt];
                s0 += sv[d] * fast_tanh(sq[d] + c[0])
                    + sv[d + 1] * fast_tanh(sq[d + 1] + c[1]);
                s1 += sv[d] * fast_tanh(sq[d] + c[2])
                    + sv[d + 1] * fast_tanh(sq[d + 1] + c[3]);
            }
            s0 += __shfl_xor_sync(0xffffffffu, s0, 1);
            s0 += __shfl_xor_sync(0xffffffffu, s0, 2);
            s1 += __shfl_xor_sync(0xffffffffu, s1, 1);
            s1 += __shfl_xor_sync(0xffffffffu, s1, 2);
            if ((lane & 3) == 0) {
                const int r0 = warp_m * 32 + mt * 16 + g;
                u_sm[r0 + 128 * warp_n] += s0;
                u_sm[r0 + 8 + 128 * warp_n] += s1;
            }
        }
    }

    __syncthreads();
    if (tid < 128)
        g_u[b * S_ + sz * 128 + tid] = u_sm[tid] + u_sm[tid + 128];
}

// ===================================================================
// Kernel C: logit = C*tanh(u); softmax over S (shift by constant C).
// ===================================================================
__global__ void softmax_kernel(float* __restrict__ out) {
    const int b = blockIdx.x, tid = threadIdx.x;
    float* logit = out + OUT_LOGIT + b * S_;
    float* probs = out + OUT_PROBS + b * S_;
    __shared__ float red[256];

    float lsum = 0.f;
    for (int s = tid; s < S_; s += 256) {
        const float l = CCLIP * fast_tanh(g_u[b * S_ + s]);
        logit[s] = l;
        lsum += expf(l - CCLIP);
    }
    red[tid] = lsum;
    __syncthreads();
    for (int o = 128; o; o >>= 1) {
        if (tid < o) red[tid] += red[tid + o];
        __syncthreads();
    }
    const float inv = 1.f / red[0];
    for (int s = tid; s < S_; s += 256)
        probs[s] = expf(logit[s] - CCLIP) * inv;
}

// ===================================================================
// Kernel D: d' partials; 16 s-chunks x 64 b, float4, deterministic.
// ===================================================================
__global__ void dprime_kernel(const float* __restrict__ src,
                              const float* __restrict__ out) {
    const float* probs = out + OUT_PROBS;
    const int sc = blockIdx.x, b = blockIdx.y, t = threadIdx.x;  // t: 0..127
    __shared__ float p_sm[128];
    p_sm[t] = probs[b * S_ + sc * 128 + t];
    __syncthreads();
    const float4* sp = (const float4*)(src + ((size_t)(b * S_ + sc * 128)) * D_) + t;
    float4 acc = make_float4(0.f, 0.f, 0.f, 0.f);
    #pragma unroll 8
    for (int s = 0; s < 128; ++s) {
        float4 x = sp[(size_t)s * 128];
        const float p = p_sm[s];
        acc.x += p * x.x; acc.y += p * x.y;
        acc.z += p * x.z; acc.w += p * x.w;
    }
    *(float4*)(g_dppart + ((size_t)sc * B_ + b) * D_ + t * 4) = acc;
}

__global__ void dpsum_kernel(float* __restrict__ out) {
    const int b = blockIdx.x, d = threadIdx.x;
    float acc = 0.f;
    #pragma unroll
    for (int sc = 0; sc < 16; ++sc)
        acc += g_dppart[((size_t)sc * B_ + b) * D_ + d];
    out[OUT_DP + b * D_ + d] = acc;
}

// ===================================================================
extern "C" void kernel_launch(void* const* d_in, const int* in_sizes, int n_in,
                              void* d_out, int out_size) {
    const float* src  = (const float*)d_in[0];  // [64, 2048, 512]
    const float* tgt  = (const float*)d_in[1];  // [64, 1, 512]
    const float* Wq   = (const float*)d_in[2];  // [512, 512]
    const float* Wref = (const float*)d_in[3];  // [512, 512]
    const float* v    = (const float*)d_in[4];  // [512]
    float* out = (float*)d_out;

    qproj_kernel<<<D_, 256>>>(tgt, Wq);
    wsplit_kernel<<<512, 512>>>(Wref);

    cudaFuncSetAttribute(fused_mma_kernel,
                         cudaFuncAttributeMaxDynamicSharedMemorySize, SM_TOTAL);
    fused_mma_kernel<<<dim3(16, B_), 256, SM_TOTAL>>>(src, v);

    softmax_kernel<<<B_, 256>>>(out);

    dprime_kernel<<<dim3(16, B_), 128>>>(src, out);
    dpsum_kernel<<<B_, D_>>>(out);
}

// round 7
// speedup vs baseline: 2.2085x; 1.1440x over previous
#include <cuda_runtime.h>
#include <cuda_bf16.h>
#include <cstdint>
#include <cstddef>

// Shape fixed by setup_inputs: B=64, S=2048, D=512, fp32.
// Outputs flattened: d_prime [64*512], probs [64*2048], logit [64*2048].
#define B_ 64
#define S_ 2048
#define D_ 512
#define CCLIP 10.0f
#define OUT_DP 0
#define OUT_PROBS (B_ * D_)
#define OUT_LOGIT (B_ * D_ + B_ * S_)

// ---- static device scratch (no allocations allowed) ----
__device__ float g_q[B_ * D_];            // q = tgt @ W_q^T
__device__ float g_u[B_ * S_];            // u logits pre-clip
__device__ float g_dppart[32 * B_ * D_];  // d' partials (32 s-chunks)
// W_ref hi/lo bf16, 32 slices in consumption order j = n*8 + ks64.
// Slice = 128 d-rows x 64 k, row = 128B, SW128-swizzled. 16KB each.
__device__ __align__(16) unsigned char g_wh[32 * 16384];
__device__ __align__(16) unsigned char g_wl[32 * 16384];

__device__ __forceinline__ uint32_t smem_u32(const void* p) {
    uint32_t a;
    asm("{ .reg .u64 t; cvta.to.shared.u64 t, %1; cvt.u32.u64 %0, t; }"
        : "=r"(a) : "l"(p));
    return a;
}
__device__ __forceinline__ uint32_t swz(uint32_t o) { return o ^ ((o >> 3) & 0x70); }

__device__ __forceinline__ void ldsm4(uint32_t* r, uint32_t addr) {
    asm volatile("ldmatrix.sync.aligned.m8n8.x4.shared.b16 {%0,%1,%2,%3}, [%4];"
        : "=r"(r[0]), "=r"(r[1]), "=r"(r[2]), "=r"(r[3]) : "r"(addr));
}
__device__ __forceinline__ void mma16816(float* c, const uint32_t* a,
                                         const uint32_t* b) {
    asm volatile(
        "mma.sync.aligned.m16n8k16.row.col.f32.bf16.bf16.f32 "
        "{%0,%1,%2,%3}, {%4,%5,%6,%7}, {%8,%9}, {%0,%1,%2,%3};"
        : "+f"(c[0]), "+f"(c[1]), "+f"(c[2]), "+f"(c[3])
        : "r"(a[0]), "r"(a[1]), "r"(a[2]), "r"(a[3]), "r"(b[0]), "r"(b[1]));
}
__device__ __forceinline__ void cp16(uint32_t saddr, const void* g) {
    asm volatile("cp.async.cg.shared.global [%0], [%1], 16;"
        :: "r"(saddr), "l"(g));
}
#define CP_COMMIT() asm volatile("cp.async.commit_group;" ::: "memory")
#define CP_WAIT1()  asm volatile("cp.async.wait_group 1;" ::: "memory")

__device__ __forceinline__ float fast_tanh(float x) {
    float e = __expf(2.0f * x);
    return 1.0f - __fdividef(2.0f, e + 1.0f);
}

// ===================================================================
// Kernel A: q[b,d] = sum_k tgt[b,k] * W_q[d,k]  (tiny)
// ===================================================================
__global__ void qproj_kernel(const float* __restrict__ tgt,
                             const float* __restrict__ Wq) {
    __shared__ float wrow[D_];
    const int d = blockIdx.x;
    for (int i = threadIdx.x; i < D_; i += blockDim.x) wrow[i] = Wq[d * D_ + i];
    __syncthreads();
    const int warp = threadIdx.x >> 5, lane = threadIdx.x & 31;
    for (int b = warp; b < B_; b += 8) {
        const float* t = tgt + b * D_;
        float p = 0.f;
        #pragma unroll 4
        for (int k = lane; k < D_; k += 32) p += t[k] * wrow[k];
        #pragma unroll
        for (int o = 16; o; o >>= 1) p += __shfl_xor_sync(0xffffffffu, p, o);
        if (lane == 0) g_q[b * D_ + d] = p;
    }
}

// ===================================================================
// Kernel W: split W_ref into hi/lo bf16 slices, pre-swizzled.
// ===================================================================
__global__ void wsplit_kernel(const float* __restrict__ Wref) {
    const int i = blockIdx.x * blockDim.x + threadIdx.x;  // 0 .. 262143
    const float w = Wref[i];
    const int d = i >> 9, k = i & 511;
    const int n = d >> 7, r = d & 127;
    const int ks = k >> 6, c = k & 63;
    const size_t off = (size_t)(n * 8 + ks) * 16384 + swz((uint32_t)(r * 128 + c * 2));
    __nv_bfloat16 hi = __float2bfloat16(w);
    *(__nv_bfloat16*)(g_wh + off) = hi;
    *(__nv_bfloat16*)(g_wl + off) = __float2bfloat16(w - __bfloat162float(hi));
}

// ===================================================================
// Kernel B: split-bf16 mma.sync GEMM + fused tanh/v-reduction.
// CTA = (b, 64-row s-tile). A (64x512 hi/lo) resident in smem, converted
// once. B streamed in 32 slices (n-major) via 2-stage cp.async ring.
// 8 warps: warp_m (0..3) = 16 s-rows, warp_n (0..1) = 64 d-cols of chunk.
// ===================================================================
#define SM_A_H 0
#define SM_A_L 65536
#define SM_B   131072
#define SM_SQ  196608
#define SM_SV  198656
#define SM_U   200704
#define SM_TOTAL 201216

__device__ __forceinline__ void prefetchB(uint32_t sb, int j, int tid) {
    const uint32_t dst = sb + SM_B + (uint32_t)(j & 1) * 32768 + tid * 16;
    const unsigned char* sh = g_wh + (size_t)j * 16384 + tid * 16;
    const unsigned char* sl = g_wl + (size_t)j * 16384 + tid * 16;
    #pragma unroll
    for (int q = 0; q < 4; ++q) {
        cp16(dst + q * 4096, sh + q * 4096);
        cp16(dst + 16384 + q * 4096, sl + q * 4096);
    }
}

__global__ __launch_bounds__(256)
void fused_mma_kernel(const float* __restrict__ src,
                      const float* __restrict__ v) {
    extern __shared__ char smem[];
    const uint32_t sb = smem_u32(smem);
    const int tid = threadIdx.x, wid = tid >> 5, lane = tid & 31;
    const int warp_m = wid & 3, warp_n = wid >> 2;
    const int sz = blockIdx.x, b = blockIdx.y;

    float* sq = (float*)(smem + SM_SQ);
    float* sv = (float*)(smem + SM_SV);
    float* u_sm = (float*)(smem + SM_U);
    for (int i = tid; i < D_; i += 256) {
        sq[i] = g_q[b * D_ + i];
        sv[i] = v[i];
    }
    if (tid < 128) u_sm[tid] = 0.f;

    // kick off B slices 0,1
    prefetchB(sb, 0, tid); CP_COMMIT();
    prefetchB(sb, 1, tid); CP_COMMIT();

    // ---- convert A (64 rows x K=512) fp32 -> hi/lo bf16, once ----
    const float* srcB = src + ((size_t)(b * S_ + sz * 64)) * D_;
    #pragma unroll 4
    for (int it = 0; it < 32; ++it) {
        const int idx = tid + it * 256;          // 0..8191 float4s
        const int r = idx >> 7, f4 = idx & 127;
        const int k0 = f4 * 4, sl = k0 >> 6, c = k0 & 63;
        float4 x = *(const float4*)(srcB + (size_t)r * D_ + k0);
        const uint32_t ob = (uint32_t)sl * 8192 + swz((uint32_t)(r * 128 + c * 2));
        __nv_bfloat162 h0 = __floats2bfloat162_rn(x.x, x.y);
        __nv_bfloat162 h1 = __floats2bfloat162_rn(x.z, x.w);
        *(__nv_bfloat162*)(smem + SM_A_H + ob) = h0;
        *(__nv_bfloat162*)(smem + SM_A_H + ob + 4) = h1;
        float lx = x.x - __low2float(h0), ly = x.y - __high2float(h0);
        float lz = x.z - __low2float(h1), lw = x.w - __high2float(h1);
        *(__nv_bfloat162*)(smem + SM_A_L + ob) = __floats2bfloat162_rn(lx, ly);
        *(__nv_bfloat162*)(smem + SM_A_L + ob + 4) = __floats2bfloat162_rn(lz, lw);
    }

    // lane-invariant fragment byte offsets (pre-swizzle)
    const uint32_t laneA = (uint32_t)(warp_m * 2048 + (lane & 15) * 128 + ((lane >> 4) << 4));
    const uint32_t laneB = (uint32_t)(warp_n * 8192 +
                                      ((lane & 7) + ((lane >> 4) & 1) * 8) * 128 +
                                      (((lane >> 3) & 1) << 4));

    float acc[8][4];
    #pragma unroll
    for (int nt = 0; nt < 8; ++nt)
        #pragma unroll
        for (int e = 0; e < 4; ++e) acc[nt][e] = 0.f;

    for (int i = 0; i < 32; ++i) {
        const int n = i >> 3, sl = i & 7;
        CP_WAIT1();
        __syncthreads();   // slice i visible to all; prior compute done

        const uint32_t aH = sb + SM_A_H + (uint32_t)sl * 8192;
        const uint32_t aL = sb + SM_A_L + (uint32_t)sl * 8192;
        const uint32_t bH = sb + SM_B + (uint32_t)(i & 1) * 32768;
        const uint32_t bL = bH + 16384;

        #pragma unroll
        for (int pass = 0; pass < 3; ++pass) {
            const uint32_t aBase = (pass == 2) ? aL : aH;
            const uint32_t bBase = (pass == 1) ? bL : bH;
            #pragma unroll
            for (int ks = 0; ks < 4; ++ks) {
                uint32_t af[4];
                ldsm4(af, aBase + swz(laneA + ks * 32));
                #pragma unroll
                for (int ntp = 0; ntp < 4; ++ntp) {
                    uint32_t bf[4];
                    ldsm4(bf, bBase + swz(laneB + (uint32_t)ntp * 2048 + ks * 32));
                    mma16816(acc[2 * ntp], af, bf);
                    mma16816(acc[2 * ntp + 1], af, bf + 2);
                }
            }
        }

        if (sl == 7) {
            // ---- epilogue for d-chunk n ----
            const int g = lane >> 2;
            float s0 = 0.f, s1 = 0.f;
            #pragma unroll
            for (int nt = 0; nt < 8; ++nt) {
                const int d = n * 128 + warp_n * 64 + nt * 8 + (lane & 3) * 2;
                s0 += sv[d] * fast_tanh(sq[d] + acc[nt][0])
                    + sv[d + 1] * fast_tanh(sq[d + 1] + acc[nt][1]);
                s1 += sv[d] * fast_tanh(sq[d] + acc[nt][2])
                    + sv[d + 1] * fast_tanh(sq[d + 1] + acc[nt][3]);
            }
            s0 += __shfl_xor_sync(0xffffffffu, s0, 1);
            s0 += __shfl_xor_sync(0xffffffffu, s0, 2);
            s1 += __shfl_xor_sync(0xffffffffu, s1, 1);
            s1 += __shfl_xor_sync(0xffffffffu, s1, 2);
            if ((lane & 3) == 0) {
                const int r0 = warp_m * 16 + g + 64 * warp_n;
                u_sm[r0] += s0;
                u_sm[r0 + 8] += s1;
            }
            #pragma unroll
            for (int nt = 0; nt < 8; ++nt)
                #pragma unroll
                for (int e = 0; e < 4; ++e) acc[nt][e] = 0.f;
        }

        __syncthreads();   // all warps done reading buf (i&1)
        if (i < 30) prefetchB(sb, i + 2, tid);
        CP_COMMIT();       // unconditional: keeps group arithmetic uniform
    }

    __syncthreads();
    if (tid < 64)
        g_u[b * S_ + sz * 64 + tid] = u_sm[tid] + u_sm[tid + 64];
}

// ===================================================================
// Kernel C: logit = C*tanh(u); softmax over S (shift by constant C).
// ===================================================================
__global__ void softmax_kernel(float* __restrict__ out) {
    const int b = blockIdx.x, tid = threadIdx.x;
    float* logit = out + OUT_LOGIT + b * S_;
    float* probs = out + OUT_PROBS + b * S_;
    __shared__ float red[256];

    float lsum = 0.f;
    for (int s = tid; s < S_; s += 256) {
        const float l = CCLIP * fast_tanh(g_u[b * S_ + s]);
        logit[s] = l;
        lsum += expf(l - CCLIP);
    }
    red[tid] = lsum;
    __syncthreads();
    for (int o = 128; o; o >>= 1) {
        if (tid < o) red[tid] += red[tid + o];
        __syncthreads();
    }
    const float inv = 1.f / red[0];
    for (int s = tid; s < S_; s += 256)
        probs[s] = expf(logit[s] - CCLIP) * inv;
}

// ===================================================================
// Kernel D: d' partials; 32 s-chunks of 64 rows, float4, deterministic.
// ===================================================================
__global__ void dprime_kernel(const float* __restrict__ src,
                              const float* __restrict__ out) {
    const float* probs = out + OUT_PROBS;
    const int sc = blockIdx.x, b = blockIdx.y, t = threadIdx.x;  // t: 0..127
    __shared__ float p_sm[64];
    if (t < 64) p_sm[t] = probs[b * S_ + sc * 64 + t];
    __syncthreads();
    const float4* sp = (const float4*)(src + ((size_t)(b * S_ + sc * 64)) * D_) + t;
    float4 acc = make_float4(0.f, 0.f, 0.f, 0.f);
    #pragma unroll 8
    for (int s = 0; s < 64; ++s) {
        float4 x = sp[(size_t)s * 128];
        const float p = p_sm[s];
        acc.x += p * x.x; acc.y += p * x.y;
        acc.z += p * x.z; acc.w += p * x.w;
    }
    *(float4*)(g_dppart + ((size_t)sc * B_ + b) * D_ + t * 4) = acc;
}

__global__ void dpsum_kernel(float* __restrict__ out) {
    const int b = blockIdx.x, d = threadIdx.x;
    float acc = 0.f;
    #pragma unroll
    for (int sc = 0; sc < 32; ++sc)
        acc += g_dppart[((size_t)sc * B_ + b) * D_ + d];
    out[OUT_DP + b * D_ + d] = acc;
}

// ===================================================================
extern "C" void kernel_launch(void* const* d_in, const int* in_sizes, int n_in,
                              void* d_out, int out_size) {
    const float* src  = (const float*)d_in[0];  // [64, 2048, 512]
    const float* tgt  = (const float*)d_in[1];  // [64, 1, 512]
    const float* Wq   = (const float*)d_in[2];  // [512, 512]
    const float* Wref = (const float*)d_in[3];  // [512, 512]
    const float* v    = (const float*)d_in[4];  // [512]
    float* out = (float*)d_out;

    qproj_kernel<<<D_, 256>>>(tgt, Wq);
    wsplit_kernel<<<512, 512>>>(Wref);

    cudaFuncSetAttribute(fused_mma_kernel,
                         cudaFuncAttributeMaxDynamicSharedMemorySize, SM_TOTAL);
    fused_mma_kernel<<<dim3(32, B_), 256, SM_TOTAL>>>(src, v);

    softmax_kernel<<<B_, 256>>>(out);

    dprime_kernel<<<dim3(32, B_), 128>>>(src, out);
    dpsum_kernel<<<B_, D_>>>(out);
}